// round 3
// baseline (speedup 1.0000x reference)
#include <cuda_runtime.h>

#define NN 32768   // columns
#define MM 512     // rows of A / X
#define KK 32      // inner dim / output rows
#define NITER 200
#define POWER_ITERS 40

typedef unsigned long long u64;

// ---- device-global scratch (no allocations allowed) ----
__device__ float g_step;
__device__ __align__(16) ulonglong2 g_AtA_q[32][8];  // [j][i4]: .x=(AtA[4i4][j],AtA[4i4+1][j]) .y=(AtA[4i4+2][j],AtA[4i4+3][j])
__device__ u64 g_AtX_p[16][NN];                      // [i2][n] = (AtX[2i2][n], AtX[2i2+1][n])

// ---- packed f32x2 helpers (sm_100+) ----
__device__ __forceinline__ u64 pack2f(float lo, float hi) {
    u64 r;
    asm("mov.b64 %0, {%1, %2};" : "=l"(r) : "r"(__float_as_uint(lo)), "r"(__float_as_uint(hi)));
    return r;
}
__device__ __forceinline__ u64 dup2f(float v) {
    u64 r;
    unsigned int u = __float_as_uint(v);
    asm("mov.b64 %0, {%1, %1};" : "=l"(r) : "r"(u));
    return r;
}
__device__ __forceinline__ void unpack2f(u64 p, float& lo, float& hi) {
    unsigned int a, b;
    asm("mov.b64 {%0, %1}, %2;" : "=r"(a), "=r"(b) : "l"(p));
    lo = __uint_as_float(a);
    hi = __uint_as_float(b);
}
__device__ __forceinline__ u64 fma2(u64 a, u64 b, u64 c) {
    u64 d;
    asm("fma.rn.f32x2 %0, %1, %2, %3;" : "=l"(d) : "l"(a), "l"(b), "l"(c));
    return d;
}

// ============================================================================
// Kernel 1 (prep): block 0 computes AtA (packed) + step = 1/||AtA||_2 via
// power iteration; blocks 1..128 compute AtX (packed over row pairs).
// These are independent, so they run concurrently in one launch.
// ============================================================================
__global__ void __launch_bounds__(256) prep_kernel(const float* __restrict__ X,
                                                   const float* __restrict__ A) {
    const int tid = threadIdx.x;

    if (blockIdx.x == 0) {
        // ---------------- AtA + spectral norm ----------------
        __shared__ float sAtA[32][32];
        const int j = tid & 31;
        const int i0 = (tid >> 5) * 4;   // 8 groups x 4 rows = 32 rows
        float a0 = 0.f, a1 = 0.f, a2 = 0.f, a3 = 0.f;
        for (int m = 0; m < MM; m++) {
            float aj = A[m * KK + j];
            a0 = fmaf(A[m * KK + i0 + 0], aj, a0);
            a1 = fmaf(A[m * KK + i0 + 1], aj, a1);
            a2 = fmaf(A[m * KK + i0 + 2], aj, a2);
            a3 = fmaf(A[m * KK + i0 + 3], aj, a3);
        }
        sAtA[i0 + 0][j] = a0;
        sAtA[i0 + 1][j] = a1;
        sAtA[i0 + 2][j] = a2;
        sAtA[i0 + 3][j] = a3;
        __syncthreads();

        // pack into g_AtA_q: 32*8 = 256 ulonglong2, one per thread
        {
            const int jj = tid >> 3;   // 0..31
            const int i4 = tid & 7;    // 0..7
            ulonglong2 q;
            q.x = pack2f(sAtA[4 * i4 + 0][jj], sAtA[4 * i4 + 1][jj]);
            q.y = pack2f(sAtA[4 * i4 + 2][jj], sAtA[4 * i4 + 3][jj]);
            g_AtA_q[jj][i4] = q;
        }

        // power iteration on warp 0: lane l holds v[l]
        if (tid < 32) {
            const int l = tid;
            float v = 1.0f, lam = 1.0f;
            for (int it = 0; it < POWER_ITERS; it++) {
                float w = 0.0f;
                #pragma unroll
                for (int jj = 0; jj < 32; jj++) {
                    float vj = __shfl_sync(0xffffffffu, v, jj);
                    w = fmaf(sAtA[l][jj], vj, w);
                }
                float n2 = w * w;
                #pragma unroll
                for (int o = 16; o; o >>= 1)
                    n2 += __shfl_xor_sync(0xffffffffu, n2, o);
                lam = sqrtf(n2);
                v = w / lam;
            }
            if (l == 0) g_step = 1.0f / lam;
        }
    } else {
        // ---------------- AtX (packed row pairs) ----------------
        __shared__ __align__(16) u64 sAp[64][16];  // [m][i2] = (A[m][2i2], A[m][2i2+1])
        const int n = (blockIdx.x - 1) * 256 + tid;
        const u64* A2 = (const u64*)A;   // float pairs, 8B aligned

        u64 acc[16];
        #pragma unroll
        for (int i2 = 0; i2 < 16; i2++) acc[i2] = 0ull;

        for (int m0 = 0; m0 < MM; m0 += 64) {
            __syncthreads();
            #pragma unroll
            for (int k = 0; k < 4; k++) {
                int idx = tid + k * 256;     // 1024 entries
                int m = idx >> 4, i2 = idx & 15;
                sAp[m][i2] = A2[(m0 + m) * 16 + i2];
            }
            __syncthreads();
            #pragma unroll 8
            for (int m = 0; m < 64; m++) {
                float x = X[(m0 + m) * NN + n];
                u64 xx = dup2f(x);
                #pragma unroll
                for (int i2 = 0; i2 < 16; i2++)
                    acc[i2] = fma2(sAp[m][i2], xx, acc[i2]);
            }
        }
        #pragma unroll
        for (int i2 = 0; i2 < 16; i2++) g_AtX_p[i2][n] = acc[i2];
    }
}

// ============================================================================
// Kernel 2: 200 FISTA iterations, one thread per column, state in registers.
// AtA broadcast from shared (LDS.128), -AtX staged in shared (saves 32 regs).
// ============================================================================
__global__ void __launch_bounds__(128) fista_kernel(float* __restrict__ out) {
    __shared__ ulonglong2 sata[32][8];          // 4 KB, packed AtA
    __shared__ u64 snatx[16][128];              // 16 KB, -AtX for this block's columns
    const int tid = threadIdx.x;
    const int n = blockIdx.x * 128 + tid;

    // cooperative copy of packed AtA (256 ulonglong2)
    {
        const ulonglong2* gq = &g_AtA_q[0][0];
        ulonglong2* sq = &sata[0][0];
        sq[tid] = gq[tid];
        sq[tid + 128] = gq[tid + 128];
    }
    // stage -AtX: 16 x 8B per thread, conflict-free (8B lane stride)
    #pragma unroll
    for (int i2 = 0; i2 < 16; i2++) {
        float lo, hi;
        unpack2f(g_AtX_p[i2][n], lo, hi);
        snatx[i2][tid] = pack2f(-lo, -hi);
    }
    const float step = g_step;
    const float nstep = -step;
    __syncthreads();

    float s[32], y[32];
    #pragma unroll
    for (int i = 0; i < 32; i++) { s[i] = 0.0f; y[i] = 0.0f; }

    float t = 1.0f;
    #pragma unroll 1
    for (int it = 0; it < NITER; it++) {
        // z = AtA @ y - AtX  (packed over row pairs; 16 independent FMA chains)
        u64 z[16];
        #pragma unroll
        for (int i2 = 0; i2 < 16; i2++) z[i2] = snatx[i2][tid];

        #pragma unroll
        for (int j = 0; j < 32; j++) {
            u64 yy = dup2f(y[j]);
            #pragma unroll
            for (int i4 = 0; i4 < 8; i4++) {
                ulonglong2 q = sata[j][i4];        // LDS.128, warp-broadcast
                z[2 * i4]     = fma2(q.x, yy, z[2 * i4]);
                z[2 * i4 + 1] = fma2(q.y, yy, z[2 * i4 + 1]);
            }
        }

        // momentum scalars (identical across threads)
        float tn = 0.5f * (1.0f + sqrtf(fmaf(4.0f * t, t, 1.0f)));
        float mu = (t - 1.0f) / tn;
        t = tn;

        // s_new = max(y - step*z, 0);  y = s_new + mu*(s_new - s);  s = s_new
        #pragma unroll
        for (int i2 = 0; i2 < 16; i2++) {
            float zlo, zhi;
            unpack2f(z[i2], zlo, zhi);
            const int i0 = 2 * i2, i1 = 2 * i2 + 1;
            float s0 = fmaxf(fmaf(nstep, zlo, y[i0]), 0.0f);
            float s1 = fmaxf(fmaf(nstep, zhi, y[i1]), 0.0f);
            y[i0] = fmaf(mu, s0 - s[i0], s0);
            y[i1] = fmaf(mu, s1 - s[i1], s1);
            s[i0] = s0;
            s[i1] = s1;
        }
    }

    // S is [32, 32768] row-major; consecutive n -> coalesced
    #pragma unroll
    for (int i = 0; i < 32; i++)
        out[i * NN + n] = s[i];
}

// ============================================================================
extern "C" void kernel_launch(void* const* d_in, const int* in_sizes, int n_in,
                              void* d_out, int out_size) {
    const float* X = (const float*)d_in[0];
    const float* A = (const float*)d_in[1];
    // defensive: identify A by its element count (512*32 = 16384)
    if (n_in >= 2 && in_sizes[0] == MM * KK && in_sizes[1] != MM * KK) {
        A = (const float*)d_in[0];
        X = (const float*)d_in[1];
    }

    prep_kernel<<<1 + NN / 256, 256>>>(X, A);
    fista_kernel<<<NN / 128, 128>>>((float*)d_out);
}

// round 4
// speedup vs baseline: 5.4095x; 5.4095x over previous
#include <cuda_runtime.h>

#define NN 32768   // columns
#define MM 512     // rows of A / X
#define KK 32      // inner dim / output rows
#define NITER 200
#define POWER_ITERS 40

// ---- device-global scratch (no allocations allowed) ----
__device__ float g_step;
__device__ __align__(16) float g_AtA[KK][KK];   // symmetric Gram matrix
__device__ float g_nAtX[KK][NN];                // negated A^T X, row-major

// ============================================================================
// Prep: block 0 -> AtA + step = 1/||AtA||_2 (power iteration);
//       blocks 1..128 -> -A^T X. Independent, run concurrently in one launch.
// ============================================================================
__global__ void __launch_bounds__(256) prep_kernel(const float* __restrict__ X,
                                                   const float* __restrict__ A) {
    const int tid = threadIdx.x;

    if (blockIdx.x == 0) {
        __shared__ float sAtA[KK][KK];
        const int j = tid & 31;
        const int i0 = (tid >> 5) * 4;       // 8 warps x 4 rows = 32 rows
        float a0 = 0.f, a1 = 0.f, a2 = 0.f, a3 = 0.f;
        for (int m = 0; m < MM; m++) {
            float aj = A[m * KK + j];
            a0 = fmaf(A[m * KK + i0 + 0], aj, a0);
            a1 = fmaf(A[m * KK + i0 + 1], aj, a1);
            a2 = fmaf(A[m * KK + i0 + 2], aj, a2);
            a3 = fmaf(A[m * KK + i0 + 3], aj, a3);
        }
        sAtA[i0 + 0][j] = a0;  g_AtA[i0 + 0][j] = a0;
        sAtA[i0 + 1][j] = a1;  g_AtA[i0 + 1][j] = a1;
        sAtA[i0 + 2][j] = a2;  g_AtA[i0 + 2][j] = a2;
        sAtA[i0 + 3][j] = a3;  g_AtA[i0 + 3][j] = a3;
        __syncthreads();

        if (tid < 32) {                       // power iteration, lane l holds v[l]
            const int l = tid;
            float v = 1.0f, lam = 1.0f;
            for (int it = 0; it < POWER_ITERS; it++) {
                float w = 0.0f;
                #pragma unroll
                for (int jj = 0; jj < 32; jj++) {
                    float vj = __shfl_sync(0xffffffffu, v, jj);
                    w = fmaf(sAtA[l][jj], vj, w);
                }
                float n2 = w * w;
                #pragma unroll
                for (int o = 16; o; o >>= 1)
                    n2 += __shfl_xor_sync(0xffffffffu, n2, o);
                lam = sqrtf(n2);
                v = w / lam;
            }
            if (l == 0) g_step = 1.0f / lam;
        }
    } else {
        // -A^T X: one thread per column n, A staged through shared in 64-row tiles
        __shared__ float4 sA4[64][8];         // [m][q] = A[m][4q..4q+3]
        const int n = (blockIdx.x - 1) * 256 + tid;
        const float4* A4 = (const float4*)A;

        float acc[32];
        #pragma unroll
        for (int i = 0; i < 32; i++) acc[i] = 0.0f;

        for (int m0 = 0; m0 < MM; m0 += 64) {
            __syncthreads();
            #pragma unroll
            for (int k = 0; k < 2; k++) {
                int idx = tid + k * 256;      // 512 float4 entries
                int m = idx >> 3, q = idx & 7;
                sA4[m][q] = A4[(m0 + m) * 8 + q];
            }
            __syncthreads();
            #pragma unroll 4
            for (int m = 0; m < 64; m++) {
                float x = X[(m0 + m) * NN + n];
                #pragma unroll
                for (int q = 0; q < 8; q++) {
                    float4 a = sA4[m][q];
                    acc[4 * q + 0] = fmaf(a.x, x, acc[4 * q + 0]);
                    acc[4 * q + 1] = fmaf(a.y, x, acc[4 * q + 1]);
                    acc[4 * q + 2] = fmaf(a.z, x, acc[4 * q + 2]);
                    acc[4 * q + 3] = fmaf(a.w, x, acc[4 * q + 3]);
                }
            }
        }
        #pragma unroll
        for (int i = 0; i < 32; i++) g_nAtX[i][n] = -acc[i];
    }
}

// ============================================================================
// FISTA: 4 threads per column; thread (n, r) owns rows 8r..8r+7.
// All state in registers; AtA broadcast from shared (conflict-free LDS.128);
// y exchanged within the quad via width-4 shuffles (compile-time lanes).
// ============================================================================
__global__ void __launch_bounds__(256) fista_kernel(float* __restrict__ out) {
    __shared__ float4 sata[KK][8];            // sata[j][q] = AtA[j][4q..4q+3] (symmetric)
    const int tid = threadIdx.x;
    const int n = blockIdx.x * 64 + (tid >> 2);
    const int r = tid & 3;                    // row group: rows 8r..8r+7

    // cooperative AtA copy: 256 float4 entries, one per thread
    ((float4*)sata)[tid] = ((const float4*)g_AtA)[tid];

    float natx[8];
    #pragma unroll
    for (int k = 0; k < 8; k++) natx[k] = g_nAtX[8 * r + k][n];

    const float nstep = -g_step;
    __syncthreads();

    float s[8], y[8];
    #pragma unroll
    for (int k = 0; k < 8; k++) { s[k] = 0.0f; y[k] = 0.0f; }

    float t = 1.0f;
    #pragma unroll 1
    for (int it = 0; it < NITER; it++) {
        float z[8];
        #pragma unroll
        for (int k = 0; k < 8; k++) z[k] = natx[k];

        #pragma unroll
        for (int j = 0; j < 32; j++) {
            // y_j lives in lane (j>>3) of this quad, register y[j&7] (both constants)
            float yj = __shfl_sync(0xffffffffu, y[j & 7], j >> 3, 4);
            float4 a0 = sata[j][2 * r + 0];   // AtA[j][8r..8r+3] == AtA[8r..8r+3][j]
            float4 a1 = sata[j][2 * r + 1];   // AtA[j][8r+4..8r+7]
            z[0] = fmaf(a0.x, yj, z[0]);
            z[1] = fmaf(a0.y, yj, z[1]);
            z[2] = fmaf(a0.z, yj, z[2]);
            z[3] = fmaf(a0.w, yj, z[3]);
            z[4] = fmaf(a1.x, yj, z[4]);
            z[5] = fmaf(a1.y, yj, z[5]);
            z[6] = fmaf(a1.z, yj, z[6]);
            z[7] = fmaf(a1.w, yj, z[7]);
        }

        float tn = 0.5f * (1.0f + sqrtf(fmaf(4.0f * t, t, 1.0f)));
        float mu = (t - 1.0f) / tn;
        t = tn;

        #pragma unroll
        for (int k = 0; k < 8; k++) {
            float sn = fmaxf(fmaf(nstep, z[k], y[k]), 0.0f);
            y[k] = fmaf(mu, sn - s[k], sn);
            s[k] = sn;
        }
    }

    #pragma unroll
    for (int k = 0; k < 8; k++)
        out[(8 * r + k) * NN + n] = s[k];
}

// ============================================================================
extern "C" void kernel_launch(void* const* d_in, const int* in_sizes, int n_in,
                              void* d_out, int out_size) {
    const float* X = (const float*)d_in[0];
    const float* A = (const float*)d_in[1];
    // defensive: identify A by its element count (512*32 = 16384)
    if (n_in >= 2 && in_sizes[0] == MM * KK && in_sizes[1] != MM * KK) {
        A = (const float*)d_in[0];
        X = (const float*)d_in[1];
    }

    prep_kernel<<<1 + NN / 256, 256>>>(X, A);
    fista_kernel<<<NN / 64, 256>>>((float*)d_out);
}

// round 5
// speedup vs baseline: 9.1041x; 1.6830x over previous
#include <cuda_runtime.h>

#define NN 32768   // columns
#define MM 512     // rows of A / X
#define KK 32      // inner dim / output rows
#define NITER 200
#define POWER_ITERS 40

// ---- device-global scratch (no allocations allowed) ----
__device__ float g_step;
__device__ float g_mu[NITER];                   // precomputed Nesterov momentum factors
__device__ __align__(16) float g_AtA[KK][KK];   // symmetric Gram matrix
__device__ float g_nAtX[KK][NN];                // negated A^T X, row-major

// ============================================================================
// Prep: block 0 -> AtA + step = 1/||AtA||_2 (power iteration) + mu table;
//       blocks 1..128 -> -A^T X. Independent, run concurrently in one launch.
// ============================================================================
__global__ void __launch_bounds__(256) prep_kernel(const float* __restrict__ X,
                                                   const float* __restrict__ A) {
    const int tid = threadIdx.x;

    if (blockIdx.x == 0) {
        __shared__ float sAtA[KK][KK];
        const int j = tid & 31;
        const int i0 = (tid >> 5) * 4;       // 8 warps x 4 rows = 32 rows
        float a0 = 0.f, a1 = 0.f, a2 = 0.f, a3 = 0.f;
        for (int m = 0; m < MM; m++) {
            float aj = A[m * KK + j];
            a0 = fmaf(A[m * KK + i0 + 0], aj, a0);
            a1 = fmaf(A[m * KK + i0 + 1], aj, a1);
            a2 = fmaf(A[m * KK + i0 + 2], aj, a2);
            a3 = fmaf(A[m * KK + i0 + 3], aj, a3);
        }
        sAtA[i0 + 0][j] = a0;  g_AtA[i0 + 0][j] = a0;
        sAtA[i0 + 1][j] = a1;  g_AtA[i0 + 1][j] = a1;
        sAtA[i0 + 2][j] = a2;  g_AtA[i0 + 2][j] = a2;
        sAtA[i0 + 3][j] = a3;  g_AtA[i0 + 3][j] = a3;
        __syncthreads();

        if (tid < 32) {                       // power iteration, lane l holds v[l]
            const int l = tid;
            float v = 1.0f, lam = 1.0f;
            for (int it = 0; it < POWER_ITERS; it++) {
                float w = 0.0f;
                #pragma unroll
                for (int jj = 0; jj < 32; jj++) {
                    float vj = __shfl_sync(0xffffffffu, v, jj);
                    w = fmaf(sAtA[l][jj], vj, w);
                }
                float n2 = w * w;
                #pragma unroll
                for (int o = 16; o; o >>= 1)
                    n2 += __shfl_xor_sync(0xffffffffu, n2, o);
                lam = sqrtf(n2);
                v = w / lam;
            }
            if (l == 0) g_step = 1.0f / lam;
        } else if (tid == 32) {               // momentum table (serial, tiny)
            float t = 1.0f;
            for (int it = 0; it < NITER; it++) {
                float tn = 0.5f * (1.0f + sqrtf(fmaf(4.0f * t, t, 1.0f)));
                g_mu[it] = (t - 1.0f) / tn;
                t = tn;
            }
        }
    } else {
        // -A^T X: one thread per column n, A staged through shared in 64-row tiles
        __shared__ float4 sA4[64][8];         // [m][q] = A[m][4q..4q+3]
        const int n = (blockIdx.x - 1) * 256 + tid;
        const float4* A4 = (const float4*)A;

        float acc[32];
        #pragma unroll
        for (int i = 0; i < 32; i++) acc[i] = 0.0f;

        for (int m0 = 0; m0 < MM; m0 += 64) {
            __syncthreads();
            #pragma unroll
            for (int k = 0; k < 2; k++) {
                int idx = tid + k * 256;      // 512 float4 entries
                int m = idx >> 3, q = idx & 7;
                sA4[m][q] = A4[(m0 + m) * 8 + q];
            }
            __syncthreads();
            #pragma unroll 4
            for (int m = 0; m < 64; m++) {
                float x = X[(m0 + m) * NN + n];
                #pragma unroll
                for (int q = 0; q < 8; q++) {
                    float4 a = sA4[m][q];
                    acc[4 * q + 0] = fmaf(a.x, x, acc[4 * q + 0]);
                    acc[4 * q + 1] = fmaf(a.y, x, acc[4 * q + 1]);
                    acc[4 * q + 2] = fmaf(a.z, x, acc[4 * q + 2]);
                    acc[4 * q + 3] = fmaf(a.w, x, acc[4 * q + 3]);
                }
            }
        }
        #pragma unroll
        for (int i = 0; i < 32; i++) g_nAtX[i][n] = -acc[i];
    }
}

// ============================================================================
// FISTA: each quad of threads owns TWO columns (n0, n0+1); thread (quad, r)
// owns rows 8r..8r+7 of both. The AtA shared loads (2x LDS.128 per j) are
// shared by both columns -> per-column L1 traffic halved vs 1-col/quad.
// y exchanged within the quad via width-4 shuffles (compile-time lanes).
// ============================================================================
__global__ void __launch_bounds__(128) fista_kernel(float* __restrict__ out) {
    __shared__ float4 sata[KK][8];            // sata[j][q] = AtA[j][4q..4q+3] (symmetric)
    __shared__ float smu[NITER];
    const int tid = threadIdx.x;
    const int q = tid >> 2;                   // quad 0..31
    const int r = tid & 3;                    // row group: rows 8r..8r+7
    const int n0 = blockIdx.x * 64 + 2 * q;   // this quad's two columns

    // cooperative AtA copy: 256 float4 entries, 128 threads x 2
    ((float4*)sata)[tid] = ((const float4*)g_AtA)[tid];
    ((float4*)sata)[tid + 128] = ((const float4*)g_AtA)[tid + 128];
    // momentum table
    #pragma unroll
    for (int i = tid; i < NITER; i += 128) smu[i] = g_mu[i];

    float natxA[8], natxB[8];
    #pragma unroll
    for (int k = 0; k < 8; k++) {
        const float2 v = *(const float2*)&g_nAtX[8 * r + k][n0];
        natxA[k] = v.x;
        natxB[k] = v.y;
    }

    const float nstep = -g_step;
    __syncthreads();

    float sA[8], yA[8], sB[8], yB[8];
    #pragma unroll
    for (int k = 0; k < 8; k++) { sA[k] = 0.0f; yA[k] = 0.0f; sB[k] = 0.0f; yB[k] = 0.0f; }

    #pragma unroll 1
    for (int it = 0; it < NITER; it++) {
        float zA[8], zB[8];
        #pragma unroll
        for (int k = 0; k < 8; k++) { zA[k] = natxA[k]; zB[k] = natxB[k]; }

        #pragma unroll
        for (int j = 0; j < 32; j++) {
            // y_j lives in lane (j>>3) of this quad, register y[j&7] (both constants)
            float yjA = __shfl_sync(0xffffffffu, yA[j & 7], j >> 3, 4);
            float yjB = __shfl_sync(0xffffffffu, yB[j & 7], j >> 3, 4);
            float4 a0 = sata[j][2 * r + 0];   // AtA[j][8r..8r+3] == AtA[8r..8r+3][j]
            float4 a1 = sata[j][2 * r + 1];   // AtA[j][8r+4..8r+7]
            zA[0] = fmaf(a0.x, yjA, zA[0]);   zB[0] = fmaf(a0.x, yjB, zB[0]);
            zA[1] = fmaf(a0.y, yjA, zA[1]);   zB[1] = fmaf(a0.y, yjB, zB[1]);
            zA[2] = fmaf(a0.z, yjA, zA[2]);   zB[2] = fmaf(a0.z, yjB, zB[2]);
            zA[3] = fmaf(a0.w, yjA, zA[3]);   zB[3] = fmaf(a0.w, yjB, zB[3]);
            zA[4] = fmaf(a1.x, yjA, zA[4]);   zB[4] = fmaf(a1.x, yjB, zB[4]);
            zA[5] = fmaf(a1.y, yjA, zA[5]);   zB[5] = fmaf(a1.y, yjB, zB[5]);
            zA[6] = fmaf(a1.z, yjA, zA[6]);   zB[6] = fmaf(a1.z, yjB, zB[6]);
            zA[7] = fmaf(a1.w, yjA, zA[7]);   zB[7] = fmaf(a1.w, yjB, zB[7]);
        }

        const float mu = smu[it];             // uniform broadcast LDS

        #pragma unroll
        for (int k = 0; k < 8; k++) {
            float snA = fmaxf(fmaf(nstep, zA[k], yA[k]), 0.0f);
            float snB = fmaxf(fmaf(nstep, zB[k], yB[k]), 0.0f);
            yA[k] = fmaf(mu, snA - sA[k], snA);
            yB[k] = fmaf(mu, snB - sB[k], snB);
            sA[k] = snA;
            sB[k] = snB;
        }
    }

    #pragma unroll
    for (int k = 0; k < 8; k++) {
        float2 v;
        v.x = sA[k];
        v.y = sB[k];
        *(float2*)&out[(8 * r + k) * NN + n0] = v;   // 8B-aligned (n0 even)
    }
}

// ============================================================================
extern "C" void kernel_launch(void* const* d_in, const int* in_sizes, int n_in,
                              void* d_out, int out_size) {
    const float* X = (const float*)d_in[0];
    const float* A = (const float*)d_in[1];
    // defensive: identify A by its element count (512*32 = 16384)
    if (n_in >= 2 && in_sizes[0] == MM * KK && in_sizes[1] != MM * KK) {
        A = (const float*)d_in[0];
        X = (const float*)d_in[1];
    }

    prep_kernel<<<1 + NN / 256, 256>>>(X, A);
    fista_kernel<<<NN / 64, 128>>>((float*)d_out);
}

// round 6
// speedup vs baseline: 9.9411x; 1.0919x over previous
#include <cuda_runtime.h>

#define NN 32768   // columns
#define MM 512     // rows of A / X
#define KK 32      // inner dim / output rows
#define NITER 200
#define POWER_ITERS 40
#define YPAD 68    // padded Y row stride (floats) to kill STS bank conflicts

// ---- device-global scratch (no allocations allowed) ----
__device__ float g_step;
__device__ float g_mu[NITER];                   // precomputed Nesterov momentum factors
__device__ __align__(16) float g_AtA[KK][KK];   // symmetric Gram matrix
__device__ float g_nAtX[KK][NN];                // negated A^T X, row-major

// ============================================================================
// Prep: block 0 -> AtA + step = 1/||AtA||_2 (power iteration) + mu table;
//       blocks 1..128 -> -A^T X. Independent, run concurrently in one launch.
// ============================================================================
__global__ void __launch_bounds__(256) prep_kernel(const float* __restrict__ X,
                                                   const float* __restrict__ A) {
    const int tid = threadIdx.x;

    if (blockIdx.x == 0) {
        __shared__ float sAtA[KK][KK];
        const int j = tid & 31;
        const int i0 = (tid >> 5) * 4;       // 8 warps x 4 rows = 32 rows
        float a0 = 0.f, a1 = 0.f, a2 = 0.f, a3 = 0.f;
        for (int m = 0; m < MM; m++) {
            float aj = A[m * KK + j];
            a0 = fmaf(A[m * KK + i0 + 0], aj, a0);
            a1 = fmaf(A[m * KK + i0 + 1], aj, a1);
            a2 = fmaf(A[m * KK + i0 + 2], aj, a2);
            a3 = fmaf(A[m * KK + i0 + 3], aj, a3);
        }
        sAtA[i0 + 0][j] = a0;  g_AtA[i0 + 0][j] = a0;
        sAtA[i0 + 1][j] = a1;  g_AtA[i0 + 1][j] = a1;
        sAtA[i0 + 2][j] = a2;  g_AtA[i0 + 2][j] = a2;
        sAtA[i0 + 3][j] = a3;  g_AtA[i0 + 3][j] = a3;
        __syncthreads();

        if (tid < 32) {                       // power iteration, lane l holds v[l]
            const int l = tid;
            float v = 1.0f, lam = 1.0f;
            for (int it = 0; it < POWER_ITERS; it++) {
                float w = 0.0f;
                #pragma unroll
                for (int jj = 0; jj < 32; jj++) {
                    float vj = __shfl_sync(0xffffffffu, v, jj);
                    w = fmaf(sAtA[l][jj], vj, w);
                }
                float n2 = w * w;
                #pragma unroll
                for (int o = 16; o; o >>= 1)
                    n2 += __shfl_xor_sync(0xffffffffu, n2, o);
                lam = sqrtf(n2);
                v = w / lam;
            }
            if (l == 0) g_step = 1.0f / lam;
        } else if (tid == 32) {               // momentum table (serial, tiny)
            float t = 1.0f;
            for (int it = 0; it < NITER; it++) {
                float tn = 0.5f * (1.0f + sqrtf(fmaf(4.0f * t, t, 1.0f)));
                g_mu[it] = (t - 1.0f) / tn;
                t = tn;
            }
        }
    } else {
        // -A^T X: one thread per column n, A staged through shared in 64-row tiles
        __shared__ float4 sA4[64][8];         // [m][q] = A[m][4q..4q+3]
        const int n = (blockIdx.x - 1) * 256 + tid;
        const float4* A4 = (const float4*)A;

        float acc[32];
        #pragma unroll
        for (int i = 0; i < 32; i++) acc[i] = 0.0f;

        for (int m0 = 0; m0 < MM; m0 += 64) {
            __syncthreads();
            #pragma unroll
            for (int k = 0; k < 2; k++) {
                int idx = tid + k * 256;      // 512 float4 entries
                int m = idx >> 3, q = idx & 7;
                sA4[m][q] = A4[(m0 + m) * 8 + q];
            }
            __syncthreads();
            #pragma unroll 4
            for (int m = 0; m < 64; m++) {
                float x = X[(m0 + m) * NN + n];
                #pragma unroll
                for (int q = 0; q < 8; q++) {
                    float4 a = sA4[m][q];
                    acc[4 * q + 0] = fmaf(a.x, x, acc[4 * q + 0]);
                    acc[4 * q + 1] = fmaf(a.y, x, acc[4 * q + 1]);
                    acc[4 * q + 2] = fmaf(a.z, x, acc[4 * q + 2]);
                    acc[4 * q + 3] = fmaf(a.w, x, acc[4 * q + 3]);
                }
            }
        }
        #pragma unroll
        for (int i = 0; i < 32; i++) g_nAtX[i][n] = -acc[i];
    }
}

// ============================================================================
// FISTA, block-GEMM layout: Y tile [32 rows x 64 cols] in shared (double-
// buffered); each thread owns 2 rows x 4 cols, with its two AtA rows cached
// in 64 REGISTERS. Matvec reads only Y from shared: one LDS.128 per j per
// thread feeding 8 FMAs -> L1 traffic ~57x lower than the shuffle scheme.
// One __syncthreads per iteration (write next buffer, flip).
// ============================================================================
__global__ void __launch_bounds__(256, 2) fista_kernel(float* __restrict__ out) {
    __shared__ float sY[2][KK][YPAD];         // double-buffered Y tile (+pad)
    __shared__ float smu[NITER];

    const int tid = threadIdx.x;
    const int cg = tid & 15;                  // col group -> cols 4cg..4cg+3
    const int rg = tid >> 4;                  // row group 0..15 -> rows 2rg, 2rg+1
    const int i0 = 2 * rg, i1 = 2 * rg + 1;
    const int c0 = 4 * cg;
    const int n0 = blockIdx.x * 64 + c0;

    // cache this thread's two AtA rows in registers (symmetric matrix)
    float a0[32], a1[32];
    #pragma unroll
    for (int q = 0; q < 8; q++) {
        float4 v0 = ((const float4*)g_AtA[i0])[q];
        float4 v1 = ((const float4*)g_AtA[i1])[q];
        a0[4 * q + 0] = v0.x; a0[4 * q + 1] = v0.y; a0[4 * q + 2] = v0.z; a0[4 * q + 3] = v0.w;
        a1[4 * q + 0] = v1.x; a1[4 * q + 1] = v1.y; a1[4 * q + 2] = v1.z; a1[4 * q + 3] = v1.w;
    }

    float4 nx0 = *(const float4*)&g_nAtX[i0][n0];
    float4 nx1 = *(const float4*)&g_nAtX[i1][n0];

    #pragma unroll
    for (int i = tid; i < NITER; i += 256) smu[i] = g_mu[i];

    // init Y buffer 0 = 0 (each thread its own entries)
    const float4 zero4 = make_float4(0.f, 0.f, 0.f, 0.f);
    *(float4*)&sY[0][i0][c0] = zero4;
    *(float4*)&sY[0][i1][c0] = zero4;

    const float nstep = -g_step;
    __syncthreads();

    float4 s0 = zero4, s1 = zero4;
    int p = 0;

    #pragma unroll 1
    for (int it = 0; it < NITER; it++) {
        float4 z0 = nx0, z1 = nx1;

        #pragma unroll
        for (int j = 0; j < 32; j++) {
            float4 y4 = *(const float4*)&sY[p][j][c0];   // LDS.128, 2-way bcast
            z0.x = fmaf(a0[j], y4.x, z0.x);
            z0.y = fmaf(a0[j], y4.y, z0.y);
            z0.z = fmaf(a0[j], y4.z, z0.z);
            z0.w = fmaf(a0[j], y4.w, z0.w);
            z1.x = fmaf(a1[j], y4.x, z1.x);
            z1.y = fmaf(a1[j], y4.y, z1.y);
            z1.z = fmaf(a1[j], y4.z, z1.z);
            z1.w = fmaf(a1[j], y4.w, z1.w);
        }

        // y_old for this thread's own rows
        float4 yo0 = *(const float4*)&sY[p][i0][c0];
        float4 yo1 = *(const float4*)&sY[p][i1][c0];
        const float mu = smu[it];

        // s_new = max(y - step*z, 0); y_new = s_new + mu*(s_new - s); s = s_new
        float4 yn0, yn1;
        {
            float t0;
            t0 = fmaxf(fmaf(nstep, z0.x, yo0.x), 0.f); yn0.x = fmaf(mu, t0 - s0.x, t0); s0.x = t0;
            t0 = fmaxf(fmaf(nstep, z0.y, yo0.y), 0.f); yn0.y = fmaf(mu, t0 - s0.y, t0); s0.y = t0;
            t0 = fmaxf(fmaf(nstep, z0.z, yo0.z), 0.f); yn0.z = fmaf(mu, t0 - s0.z, t0); s0.z = t0;
            t0 = fmaxf(fmaf(nstep, z0.w, yo0.w), 0.f); yn0.w = fmaf(mu, t0 - s0.w, t0); s0.w = t0;
            t0 = fmaxf(fmaf(nstep, z1.x, yo1.x), 0.f); yn1.x = fmaf(mu, t0 - s1.x, t0); s1.x = t0;
            t0 = fmaxf(fmaf(nstep, z1.y, yo1.y), 0.f); yn1.y = fmaf(mu, t0 - s1.y, t0); s1.y = t0;
            t0 = fmaxf(fmaf(nstep, z1.z, yo1.z), 0.f); yn1.z = fmaf(mu, t0 - s1.z, t0); s1.z = t0;
            t0 = fmaxf(fmaf(nstep, z1.w, yo1.w), 0.f); yn1.w = fmaf(mu, t0 - s1.w, t0); s1.w = t0;
        }

        // write next buffer, flip
        *(float4*)&sY[p ^ 1][i0][c0] = yn0;
        *(float4*)&sY[p ^ 1][i1][c0] = yn1;
        __syncthreads();
        p ^= 1;
    }

    // S is [32, 32768] row-major; warp covers contiguous 64-col span
    *(float4*)&out[i0 * NN + n0] = s0;
    *(float4*)&out[i1 * NN + n0] = s1;
}

// ============================================================================
extern "C" void kernel_launch(void* const* d_in, const int* in_sizes, int n_in,
                              void* d_out, int out_size) {
    const float* X = (const float*)d_in[0];
    const float* A = (const float*)d_in[1];
    // defensive: identify A by its element count (512*32 = 16384)
    if (n_in >= 2 && in_sizes[0] == MM * KK && in_sizes[1] != MM * KK) {
        A = (const float*)d_in[0];
        X = (const float*)d_in[1];
    }

    prep_kernel<<<1 + NN / 256, 256>>>(X, A);
    fista_kernel<<<NN / 64, 256>>>((float*)d_out);
}

// round 7
// speedup vs baseline: 15.2151x; 1.5305x over previous
#include <cuda_runtime.h>

#define NN 32768   // columns
#define MM 512     // rows of A / X
#define KK 32      // inner dim / output rows
#define NITER 200
#define POWER_ITERS 40
#define YS 36      // sY row stride in floats (STS spreads to min 4 phases)

typedef unsigned long long u64;

// ---- device-global scratch (no allocations allowed) ----
__device__ float g_step;
__device__ float g_mu[NITER];                   // precomputed Nesterov momentum factors
__device__ __align__(16) float g_AtA[KK][KK];   // symmetric Gram matrix
__device__ float g_nAtX[KK][NN];                // negated A^T X, row-major

// ---- packed f32x2 helpers (sm_100a) ----
__device__ __forceinline__ u64 pack2f(float lo, float hi) {
    u64 r;
    asm("mov.b64 %0, {%1, %2};" : "=l"(r) : "r"(__float_as_uint(lo)), "r"(__float_as_uint(hi)));
    return r;
}
__device__ __forceinline__ u64 dup2f(float v) {
    u64 r;
    unsigned int u = __float_as_uint(v);
    asm("mov.b64 %0, {%1, %1};" : "=l"(r) : "r"(u));
    return r;
}
__device__ __forceinline__ void unpack2f(u64 p, float& lo, float& hi) {
    unsigned int a, b;
    asm("mov.b64 {%0, %1}, %2;" : "=r"(a), "=r"(b) : "l"(p));
    lo = __uint_as_float(a);
    hi = __uint_as_float(b);
}
__device__ __forceinline__ u64 fma2(u64 a, u64 b, u64 c) {
    u64 d;
    asm("fma.rn.f32x2 %0, %1, %2, %3;" : "=l"(d) : "l"(a), "l"(b), "l"(c));
    return d;
}

// ============================================================================
// Prep: block 0 -> AtA + step = 1/||AtA||_2 (power iteration) + mu table;
//       blocks 1..128 -> -A^T X. Independent, run concurrently in one launch.
// ============================================================================
__global__ void __launch_bounds__(256) prep_kernel(const float* __restrict__ X,
                                                   const float* __restrict__ A) {
    const int tid = threadIdx.x;

    if (blockIdx.x == 0) {
        __shared__ float sAtA[KK][KK];
        const int j = tid & 31;
        const int i0 = (tid >> 5) * 4;       // 8 warps x 4 rows = 32 rows
        float a0 = 0.f, a1 = 0.f, a2 = 0.f, a3 = 0.f;
        for (int m = 0; m < MM; m++) {
            float aj = A[m * KK + j];
            a0 = fmaf(A[m * KK + i0 + 0], aj, a0);
            a1 = fmaf(A[m * KK + i0 + 1], aj, a1);
            a2 = fmaf(A[m * KK + i0 + 2], aj, a2);
            a3 = fmaf(A[m * KK + i0 + 3], aj, a3);
        }
        sAtA[i0 + 0][j] = a0;  g_AtA[i0 + 0][j] = a0;
        sAtA[i0 + 1][j] = a1;  g_AtA[i0 + 1][j] = a1;
        sAtA[i0 + 2][j] = a2;  g_AtA[i0 + 2][j] = a2;
        sAtA[i0 + 3][j] = a3;  g_AtA[i0 + 3][j] = a3;
        __syncthreads();

        if (tid < 32) {                       // power iteration, lane l holds v[l]
            const int l = tid;
            float v = 1.0f, lam = 1.0f;
            for (int it = 0; it < POWER_ITERS; it++) {
                float w = 0.0f;
                #pragma unroll
                for (int jj = 0; jj < 32; jj++) {
                    float vj = __shfl_sync(0xffffffffu, v, jj);
                    w = fmaf(sAtA[l][jj], vj, w);
                }
                float n2 = w * w;
                #pragma unroll
                for (int o = 16; o; o >>= 1)
                    n2 += __shfl_xor_sync(0xffffffffu, n2, o);
                lam = sqrtf(n2);
                v = w / lam;
            }
            if (l == 0) g_step = 1.0f / lam;
        } else if (tid == 32) {               // momentum table (serial, tiny)
            float t = 1.0f;
            for (int it = 0; it < NITER; it++) {
                float tn = 0.5f * (1.0f + sqrtf(fmaf(4.0f * t, t, 1.0f)));
                g_mu[it] = (t - 1.0f) / tn;
                t = tn;
            }
        }
    } else {
        // -A^T X: one thread per column n, A staged through shared in 64-row tiles
        __shared__ float4 sA4[64][8];         // [m][q] = A[m][4q..4q+3]
        const int n = (blockIdx.x - 1) * 256 + tid;
        const float4* A4 = (const float4*)A;

        float acc[32];
        #pragma unroll
        for (int i = 0; i < 32; i++) acc[i] = 0.0f;

        for (int m0 = 0; m0 < MM; m0 += 64) {
            __syncthreads();
            #pragma unroll
            for (int k = 0; k < 2; k++) {
                int idx = tid + k * 256;      // 512 float4 entries
                int m = idx >> 3, q = idx & 7;
                sA4[m][q] = A4[(m0 + m) * 8 + q];
            }
            __syncthreads();
            #pragma unroll 4
            for (int m = 0; m < 64; m++) {
                float x = X[(m0 + m) * NN + n];
                #pragma unroll
                for (int q = 0; q < 8; q++) {
                    float4 a = sA4[m][q];
                    acc[4 * q + 0] = fmaf(a.x, x, acc[4 * q + 0]);
                    acc[4 * q + 1] = fmaf(a.y, x, acc[4 * q + 1]);
                    acc[4 * q + 2] = fmaf(a.z, x, acc[4 * q + 2]);
                    acc[4 * q + 3] = fmaf(a.w, x, acc[4 * q + 3]);
                }
            }
        }
        #pragma unroll
        for (int i = 0; i < 32; i++) g_nAtX[i][n] = -acc[i];
    }
}

// ============================================================================
// FISTA: each WARP owns a 16-column stripe and ALL 32 rows -> warps are fully
// independent (syncwarp only, no block barrier). Thread = 4 rows x 4 cols;
// its 4 AtA rows live in 128 registers; per j ONE LDS.128 of y feeds 16 FMAs
// (8 FFMA2, columns packed in f32x2). LDS-instr count per element is half of
// the previous layout -> LSU-dispatch (the measured binding pipe) halves.
// ============================================================================
__global__ void __launch_bounds__(128) fista_kernel(float* __restrict__ out) {
    __shared__ float sY[4][KK][YS];           // per-warp y tile (single buffer)
    __shared__ float smu[NITER];

    const int tid = threadIdx.x;
    const int w = tid >> 5;                   // warp id 0..3
    const int lane = tid & 31;
    const int rg = lane >> 2;                 // rowgroup 0..7 -> rows 4rg..4rg+3
    const int hg = lane & 3;                  // colgroup 0..3 -> cols 4hg..4hg+3
    const int r0 = 4 * rg;
    const int c0 = 4 * hg;
    const int n0 = blockIdx.x * 64 + w * 16 + c0;

    // this thread's 4 AtA rows in registers (128 regs)
    float a[4][32];
    #pragma unroll
    for (int r = 0; r < 4; r++) {
        #pragma unroll
        for (int q = 0; q < 8; q++) {
            float4 v = ((const float4*)g_AtA[r0 + r])[q];
            a[r][4 * q + 0] = v.x; a[r][4 * q + 1] = v.y;
            a[r][4 * q + 2] = v.z; a[r][4 * q + 3] = v.w;
        }
    }

    // -AtX for this thread's 4x4 patch, packed as col-pairs
    u64 nx[4][2];
    #pragma unroll
    for (int r = 0; r < 4; r++) {
        float4 v = *(const float4*)&g_nAtX[r0 + r][n0];
        nx[r][0] = pack2f(v.x, v.y);
        nx[r][1] = pack2f(v.z, v.w);
    }

    #pragma unroll
    for (int i = tid; i < NITER; i += 128) smu[i] = g_mu[i];

    // zero this thread's y entries
    const float4 zero4 = make_float4(0.f, 0.f, 0.f, 0.f);
    #pragma unroll
    for (int r = 0; r < 4; r++)
        *(float4*)&sY[w][r0 + r][c0] = zero4;

    const float nstep = -g_step;
    __syncthreads();                          // smu + initial y visible

    float s[4][4], yo[4][4];
    #pragma unroll
    for (int r = 0; r < 4; r++)
        #pragma unroll
        for (int k = 0; k < 4; k++) { s[r][k] = 0.0f; yo[r][k] = 0.0f; }

    #pragma unroll 1
    for (int it = 0; it < NITER; it++) {
        u64 z[4][2];
        #pragma unroll
        for (int r = 0; r < 4; r++) { z[r][0] = nx[r][0]; z[r][1] = nx[r][1]; }

        #pragma unroll
        for (int j = 0; j < 32; j++) {
            // one LDS.128: y[j] for this thread's 4 cols (broadcast across rowgroups)
            ulonglong2 yy = *(const ulonglong2*)&sY[w][j][c0];
            u64 d0 = dup2f(a[0][j]);
            u64 d1 = dup2f(a[1][j]);
            u64 d2 = dup2f(a[2][j]);
            u64 d3 = dup2f(a[3][j]);
            z[0][0] = fma2(d0, yy.x, z[0][0]);  z[0][1] = fma2(d0, yy.y, z[0][1]);
            z[1][0] = fma2(d1, yy.x, z[1][0]);  z[1][1] = fma2(d1, yy.y, z[1][1]);
            z[2][0] = fma2(d2, yy.x, z[2][0]);  z[2][1] = fma2(d2, yy.y, z[2][1]);
            z[3][0] = fma2(d3, yy.x, z[3][0]);  z[3][1] = fma2(d3, yy.y, z[3][1]);
        }

        const float mu = smu[it];

        __syncwarp();                         // all lanes done reading old y
        #pragma unroll
        for (int r = 0; r < 4; r++) {
            float zv[4];
            unpack2f(z[r][0], zv[0], zv[1]);
            unpack2f(z[r][1], zv[2], zv[3]);
            float4 yn;
            float sn;
            sn = fmaxf(fmaf(nstep, zv[0], yo[r][0]), 0.f); yn.x = fmaf(mu, sn - s[r][0], sn); s[r][0] = sn; yo[r][0] = yn.x;
            sn = fmaxf(fmaf(nstep, zv[1], yo[r][1]), 0.f); yn.y = fmaf(mu, sn - s[r][1], sn); s[r][1] = sn; yo[r][1] = yn.y;
            sn = fmaxf(fmaf(nstep, zv[2], yo[r][2]), 0.f); yn.z = fmaf(mu, sn - s[r][2], sn); s[r][2] = sn; yo[r][2] = yn.z;
            sn = fmaxf(fmaf(nstep, zv[3], yo[r][3]), 0.f); yn.w = fmaf(mu, sn - s[r][3], sn); s[r][3] = sn; yo[r][3] = yn.w;
            *(float4*)&sY[w][r0 + r][c0] = yn;
        }
        __syncwarp();                         // new y visible before next matvec
    }

    // S is [32, 32768] row-major
    #pragma unroll
    for (int r = 0; r < 4; r++) {
        float4 v = make_float4(s[r][0], s[r][1], s[r][2], s[r][3]);
        *(float4*)&out[(r0 + r) * NN + n0] = v;
    }
}

// ============================================================================
extern "C" void kernel_launch(void* const* d_in, const int* in_sizes, int n_in,
                              void* d_out, int out_size) {
    const float* X = (const float*)d_in[0];
    const float* A = (const float*)d_in[1];
    // defensive: identify A by its element count (512*32 = 16384)
    if (n_in >= 2 && in_sizes[0] == MM * KK && in_sizes[1] != MM * KK) {
        A = (const float*)d_in[0];
        X = (const float*)d_in[1];
    }

    prep_kernel<<<1 + NN / 256, 256>>>(X, A);
    fista_kernel<<<NN / 64, 128>>>((float*)d_out);
}